// round 12
// baseline (speedup 1.0000x reference)
#include <cuda_runtime.h>
#include <cuda_bf16.h>
#include <cstdint>

// Blockwise 8x8 2D DCT, out = D @ X @ D^T over [16,32,512,512] fp32.
// FINAL SHAPE — at the measured mixed-R/W HBM ceiling (~6.8 TB/s, traffic
// exactly compulsory: 512 MB in + 512 MB out).
//
// Warp tile = 8 rows x 128 cols (16 DCT blocks). All gmem via LDG.128/STG.128,
// each instruction covering 4 COMPLETE 128B lines (zero sector fragmentation):
//   8x LDG.128.CG : lane = float4 strip, cols 4L..4L+3, rows 0..7
//                   (L2-only: read-once stream, keep L1 free for smem/stores)
//   vertical DCT  : float4 component-wise butterfly (DCT matrix folded to
//                   immediates -> FFMA-imm, rt=1)
//   smem bounce A : 8x STS.128 (CF) -> 8x LDS.128 row gather (CF)
//   horizontal DCT: 4 block-rows per lane (scalar butterfly)
//   smem bounce B : 8x STS.128 (CF) -> 8x LDS.128 + 8x STG.128.CS
// One warp-private buffer (RS=132: all phases bank-conflict-free).
// One tile per warp; latency hiding via occupancy (4 CTAs/SM).

#define C0f 0.35355339059327373f
#define C1f 0.49039264020161522f
#define C2f 0.46193976625564338f
#define C3f 0.41573480615127262f
#define C4f 0.35355339059327379f
#define C5f 0.27778511650980111f
#define C6f 0.19134171618254489f
#define C7f 0.09754516100806413f

__device__ __forceinline__ void dct8(const float x[8], float y[8])
{
    const float s0 = x[0] + x[7], s1 = x[1] + x[6];
    const float s2 = x[2] + x[5], s3 = x[3] + x[4];
    const float d0 = x[0] - x[7], d1 = x[1] - x[6];
    const float d2 = x[2] - x[5], d3 = x[3] - x[4];
    const float a = s0 + s3, b = s1 + s2;
    const float e = s0 - s3, f = s1 - s2;

    y[0] = C0f * (a + b);
    y[4] = C4f * (a - b);
    y[2] = fmaf(C2f, e,  C6f * f);
    y[6] = fmaf(C6f, e, -C2f * f);
    y[1] = fmaf(C1f, d0, fmaf( C3f, d1, fmaf( C5f, d2,  C7f * d3)));
    y[3] = fmaf(C3f, d0, fmaf(-C7f, d1, fmaf(-C1f, d2, -C5f * d3)));
    y[5] = fmaf(C5f, d0, fmaf(-C1f, d1, fmaf( C7f, d2,  C3f * d3)));
    y[7] = fmaf(C7f, d0, fmaf(-C5f, d1, fmaf( C3f, d2, -C1f * d3)));
}

__device__ __forceinline__ float4 f4add(float4 a, float4 b){ return make_float4(a.x+b.x, a.y+b.y, a.z+b.z, a.w+b.w); }
__device__ __forceinline__ float4 f4sub(float4 a, float4 b){ return make_float4(a.x-b.x, a.y-b.y, a.z-b.z, a.w-b.w); }
__device__ __forceinline__ float4 f4scale(float s, float4 a){ return make_float4(s*a.x, s*a.y, s*a.z, s*a.w); }
__device__ __forceinline__ float4 f4fma(float s, float4 a, float4 c){
    return make_float4(fmaf(s,a.x,c.x), fmaf(s,a.y,c.y), fmaf(s,a.z,c.z), fmaf(s,a.w,c.w));
}

__device__ __forceinline__ void dct8v(const float4 x[8], float4 y[8])
{
    const float4 s0 = f4add(x[0], x[7]), s1 = f4add(x[1], x[6]);
    const float4 s2 = f4add(x[2], x[5]), s3 = f4add(x[3], x[4]);
    const float4 d0 = f4sub(x[0], x[7]), d1 = f4sub(x[1], x[6]);
    const float4 d2 = f4sub(x[2], x[5]), d3 = f4sub(x[3], x[4]);
    const float4 a = f4add(s0, s3), b = f4add(s1, s2);
    const float4 e = f4sub(s0, s3), f = f4sub(s1, s2);

    y[0] = f4scale(C0f, f4add(a, b));
    y[4] = f4scale(C4f, f4sub(a, b));
    y[2] = f4fma(C2f, e, f4scale( C6f, f));
    y[6] = f4fma(C6f, e, f4scale(-C2f, f));
    y[1] = f4fma(C1f, d0, f4fma( C3f, d1, f4fma( C5f, d2, f4scale( C7f, d3))));
    y[3] = f4fma(C3f, d0, f4fma(-C7f, d1, f4fma(-C1f, d2, f4scale(-C5f, d3))));
    y[5] = f4fma(C5f, d0, f4fma(-C1f, d1, f4fma( C7f, d2, f4scale( C3f, d3))));
    y[7] = f4fma(C7f, d0, f4fma(-C5f, d1, f4fma( C3f, d2, f4scale(-C1f, d3))));
}

#define W_DIM 512
#define RS 132          // smem row stride in floats (128 + 4 pad; 16B multiple)

__device__ __forceinline__ size_t tile_base(unsigned t)
{
    // 4 tiles (128 cols each) across a 512-wide strip of 8 rows
    return (size_t)(t >> 2) * (8u * W_DIM) + (size_t)((t & 3u) << 7);
}

__global__ __launch_bounds__(256, 4)
void dct8x8_kernel(const float* __restrict__ x, float* __restrict__ out)
{
    __shared__ float buf_all[8][8 * RS];     // one private buffer per warp
    const unsigned wq = threadIdx.x >> 5;
    float* __restrict__ buf = buf_all[wq];

    const unsigned lane = threadIdx.x & 31u;
    const unsigned k2   = lane & 7u;         // row handled in horizontal phase
    const unsigned bhi  = lane >> 3;         // block sub-index
    const unsigned tile = blockIdx.x * (blockDim.x >> 5) + wq;

    // 8x LDG.128.CG (L2-only; each covers 4 full 128B lines warp-wide)
    float4 cur[8];
    {
        const float* __restrict__ p = x + tile_base(tile) + 4u * lane;
        #pragma unroll
        for (int i = 0; i < 8; i++)
            cur[i] = __ldcg(reinterpret_cast<const float4*>(p + (size_t)i * W_DIM));
    }

    // vertical DCT on 4 columns at once
    float4 y[8];
    dct8v(cur, y);

    // bounce A scatter: buf[k][4*lane..] (CF per phase)
    #pragma unroll
    for (int k = 0; k < 8; k++)
        *reinterpret_cast<float4*>(buf + k * RS + 4u * lane) = y[k];
    __syncwarp();

    // gather 4 block-rows per lane: task j -> block b = 4j+bhi, row k2
    float g[4][8];
    #pragma unroll
    for (int j = 0; j < 4; j++) {
        const unsigned b8 = (4u * j + bhi) << 3;
        const float4 a = *reinterpret_cast<const float4*>(buf + k2 * RS + b8);
        const float4 c = *reinterpret_cast<const float4*>(buf + k2 * RS + b8 + 4);
        g[j][0]=a.x; g[j][1]=a.y; g[j][2]=a.z; g[j][3]=a.w;
        g[j][4]=c.x; g[j][5]=c.y; g[j][6]=c.z; g[j][7]=c.w;
    }
    __syncwarp();   // all reads done before in-place overwrite

    // horizontal DCT + bounce B scatter (same slots, CF)
    #pragma unroll
    for (int j = 0; j < 4; j++) {
        float z[8];
        dct8(g[j], z);
        const unsigned b8 = (4u * j + bhi) << 3;
        float* __restrict__ q = buf + k2 * RS + b8;
        *reinterpret_cast<float4*>(q)     = make_float4(z[0], z[1], z[2], z[3]);
        *reinterpret_cast<float4*>(q + 4) = make_float4(z[4], z[5], z[6], z[7]);
    }
    __syncwarp();

    // clean full-line stores: 8x STG.128, 128 contiguous floats per warp row
    float* __restrict__ o = out + tile_base(tile) + 4u * lane;
    #pragma unroll
    for (int k = 0; k < 8; k++) {
        const float4 w = *reinterpret_cast<const float4*>(buf + k * RS + 4u * lane);
        __stcs(reinterpret_cast<float4*>(o + (size_t)k * W_DIM), w);
    }
}

extern "C" void kernel_launch(void* const* d_in, const int* in_sizes, int n_in,
                              void* d_out, int out_size)
{
    const float* x = (const float*)d_in[0];
    float* out     = (float*)d_out;

    // per CTA: 8 warps * 1024 elements = 8192 elements
    const int grid = out_size / 8192;
    dct8x8_kernel<<<grid, 256>>>(x, out);
}

// round 13
// speedup vs baseline: 1.1858x; 1.1858x over previous
#include <cuda_runtime.h>
#include <cuda_bf16.h>
#include <cstdint>

// Blockwise 8x8 2D DCT, out = D @ X @ D^T over [16,32,512,512] fp32.
// FINAL (= round-11 optimum) — at the measured mixed-R/W HBM ceiling
// (~6.77 TB/s, 85.5% of spec; traffic exactly compulsory: 512 MB + 512 MB).
//
// Warp tile = 8 rows x 128 cols (16 DCT blocks). All gmem via LDG.128/STG.128
// with .CS (streaming, L1-allocating — NOT .CG, which fragments L1tex
// wavefronts to sector granularity and cost 19% in round 12):
//   8x LDG.128.CS : lane = float4 strip, cols 4L..4L+3, rows 0..7
//                   (each instruction covers 4 complete 128B lines)
//   vertical DCT  : float4 component-wise butterfly (DCT matrix folded to
//                   immediates -> FFMA-imm, rt=1 on sm_103a)
//   smem bounce A : 8x STS.128 (CF) -> 8x LDS.128 row gather (CF)
//   horizontal DCT: 4 block-rows per lane (scalar butterfly)
//   smem bounce B : 8x STS.128 (CF) -> 8x LDS.128 + 8x STG.128.CS
// One warp-private buffer (RS=132: all four phases bank-conflict-free).
// One tile per warp; latency hiding via occupancy (4 CTAs/SM).

#define C0f 0.35355339059327373f
#define C1f 0.49039264020161522f
#define C2f 0.46193976625564338f
#define C3f 0.41573480615127262f
#define C4f 0.35355339059327379f
#define C5f 0.27778511650980111f
#define C6f 0.19134171618254489f
#define C7f 0.09754516100806413f

__device__ __forceinline__ void dct8(const float x[8], float y[8])
{
    const float s0 = x[0] + x[7], s1 = x[1] + x[6];
    const float s2 = x[2] + x[5], s3 = x[3] + x[4];
    const float d0 = x[0] - x[7], d1 = x[1] - x[6];
    const float d2 = x[2] - x[5], d3 = x[3] - x[4];
    const float a = s0 + s3, b = s1 + s2;
    const float e = s0 - s3, f = s1 - s2;

    y[0] = C0f * (a + b);
    y[4] = C4f * (a - b);
    y[2] = fmaf(C2f, e,  C6f * f);
    y[6] = fmaf(C6f, e, -C2f * f);
    y[1] = fmaf(C1f, d0, fmaf( C3f, d1, fmaf( C5f, d2,  C7f * d3)));
    y[3] = fmaf(C3f, d0, fmaf(-C7f, d1, fmaf(-C1f, d2, -C5f * d3)));
    y[5] = fmaf(C5f, d0, fmaf(-C1f, d1, fmaf( C7f, d2,  C3f * d3)));
    y[7] = fmaf(C7f, d0, fmaf(-C5f, d1, fmaf( C3f, d2, -C1f * d3)));
}

__device__ __forceinline__ float4 f4add(float4 a, float4 b){ return make_float4(a.x+b.x, a.y+b.y, a.z+b.z, a.w+b.w); }
__device__ __forceinline__ float4 f4sub(float4 a, float4 b){ return make_float4(a.x-b.x, a.y-b.y, a.z-b.z, a.w-b.w); }
__device__ __forceinline__ float4 f4scale(float s, float4 a){ return make_float4(s*a.x, s*a.y, s*a.z, s*a.w); }
__device__ __forceinline__ float4 f4fma(float s, float4 a, float4 c){
    return make_float4(fmaf(s,a.x,c.x), fmaf(s,a.y,c.y), fmaf(s,a.z,c.z), fmaf(s,a.w,c.w));
}

__device__ __forceinline__ void dct8v(const float4 x[8], float4 y[8])
{
    const float4 s0 = f4add(x[0], x[7]), s1 = f4add(x[1], x[6]);
    const float4 s2 = f4add(x[2], x[5]), s3 = f4add(x[3], x[4]);
    const float4 d0 = f4sub(x[0], x[7]), d1 = f4sub(x[1], x[6]);
    const float4 d2 = f4sub(x[2], x[5]), d3 = f4sub(x[3], x[4]);
    const float4 a = f4add(s0, s3), b = f4add(s1, s2);
    const float4 e = f4sub(s0, s3), f = f4sub(s1, s2);

    y[0] = f4scale(C0f, f4add(a, b));
    y[4] = f4scale(C4f, f4sub(a, b));
    y[2] = f4fma(C2f, e, f4scale( C6f, f));
    y[6] = f4fma(C6f, e, f4scale(-C2f, f));
    y[1] = f4fma(C1f, d0, f4fma( C3f, d1, f4fma( C5f, d2, f4scale( C7f, d3))));
    y[3] = f4fma(C3f, d0, f4fma(-C7f, d1, f4fma(-C1f, d2, f4scale(-C5f, d3))));
    y[5] = f4fma(C5f, d0, f4fma(-C1f, d1, f4fma( C7f, d2, f4scale( C3f, d3))));
    y[7] = f4fma(C7f, d0, f4fma(-C5f, d1, f4fma( C3f, d2, f4scale(-C1f, d3))));
}

#define W_DIM 512
#define RS 132          // smem row stride in floats (128 + 4 pad; 16B multiple)

__device__ __forceinline__ size_t tile_base(unsigned t)
{
    // 4 tiles (128 cols each) across a 512-wide strip of 8 rows
    return (size_t)(t >> 2) * (8u * W_DIM) + (size_t)((t & 3u) << 7);
}

__global__ __launch_bounds__(256, 4)
void dct8x8_kernel(const float* __restrict__ x, float* __restrict__ out)
{
    __shared__ float buf_all[8][8 * RS];     // one private buffer per warp
    const unsigned wq = threadIdx.x >> 5;
    float* __restrict__ buf = buf_all[wq];

    const unsigned lane = threadIdx.x & 31u;
    const unsigned k2   = lane & 7u;         // row handled in horizontal phase
    const unsigned bhi  = lane >> 3;         // block sub-index
    const unsigned tile = blockIdx.x * (blockDim.x >> 5) + wq;

    // 8x LDG.128.CS (each covers 4 full 128B lines warp-wide)
    float4 cur[8];
    {
        const float* __restrict__ p = x + tile_base(tile) + 4u * lane;
        #pragma unroll
        for (int i = 0; i < 8; i++)
            cur[i] = __ldcs(reinterpret_cast<const float4*>(p + (size_t)i * W_DIM));
    }

    // vertical DCT on 4 columns at once
    float4 y[8];
    dct8v(cur, y);

    // bounce A scatter: buf[k][4*lane..] (CF per phase)
    #pragma unroll
    for (int k = 0; k < 8; k++)
        *reinterpret_cast<float4*>(buf + k * RS + 4u * lane) = y[k];
    __syncwarp();

    // gather 4 block-rows per lane: task j -> block b = 4j+bhi, row k2
    float g[4][8];
    #pragma unroll
    for (int j = 0; j < 4; j++) {
        const unsigned b8 = (4u * j + bhi) << 3;
        const float4 a = *reinterpret_cast<const float4*>(buf + k2 * RS + b8);
        const float4 c = *reinterpret_cast<const float4*>(buf + k2 * RS + b8 + 4);
        g[j][0]=a.x; g[j][1]=a.y; g[j][2]=a.z; g[j][3]=a.w;
        g[j][4]=c.x; g[j][5]=c.y; g[j][6]=c.z; g[j][7]=c.w;
    }
    __syncwarp();   // all reads done before in-place overwrite

    // horizontal DCT + bounce B scatter (same slots, CF)
    #pragma unroll
    for (int j = 0; j < 4; j++) {
        float z[8];
        dct8(g[j], z);
        const unsigned b8 = (4u * j + bhi) << 3;
        float* __restrict__ q = buf + k2 * RS + b8;
        *reinterpret_cast<float4*>(q)     = make_float4(z[0], z[1], z[2], z[3]);
        *reinterpret_cast<float4*>(q + 4) = make_float4(z[4], z[5], z[6], z[7]);
    }
    __syncwarp();

    // clean full-line stores: 8x STG.128, 128 contiguous floats per warp row
    float* __restrict__ o = out + tile_base(tile) + 4u * lane;
    #pragma unroll
    for (int k = 0; k < 8; k++) {
        const float4 w = *reinterpret_cast<const float4*>(buf + k * RS + 4u * lane);
        __stcs(reinterpret_cast<float4*>(o + (size_t)k * W_DIM), w);
    }
}

extern "C" void kernel_launch(void* const* d_in, const int* in_sizes, int n_in,
                              void* d_out, int out_size)
{
    const float* x = (const float*)d_in[0];
    float* out     = (float*)d_out;

    // per CTA: 8 warps * 1024 elements = 8192 elements
    const int grid = out_size / 8192;
    dct8x8_kernel<<<grid, 256>>>(x, out);
}